// round 16
// baseline (speedup 1.0000x reference)
#include <cuda_runtime.h>
#include <cuda_fp16.h>
#include <cstdint>

// ---------------------------------------------------------------------------
// Problem constants
// ---------------------------------------------------------------------------
#define NC_MAX 50000
#define NG_MAX 30000
#define FD 128
#define ECC_MAX 500000
#define ECG_MAX 400000
#define EGC_MAX 400000

// fp16 feature scratch
#define HOFF_YCC ((size_t)0)
#define HOFF_YCG ((size_t)NC_MAX * FD)
#define HOFF_YGC ((size_t)2 * NC_MAX * FD)
#define HOFF_H1C (HOFF_YGC + (size_t)NG_MAX * FD)
#define HOFF_H1G (HOFF_H1C + (size_t)NC_MAX * FD)
#define HSCRATCH_TOTAL (HOFF_H1G + (size_t)NG_MAX * FD)

__device__ __align__(16) __half g_hscratch[HSCRATCH_TOTAL];

// Degree arrays. Layout: [invs_cc | invs_cg | invs_gc | invd_cc | invd_gc | invd_cg | desc]
#define DOFF_INVS_CC 0
#define DOFF_INVS_CG (DOFF_INVS_CC + NC_MAX)
#define DOFF_INVS_GC (DOFF_INVS_CG + NC_MAX)
#define INVS_TOTAL   (DOFF_INVS_GC + NG_MAX)
#define DOFF_INVD_CC (INVS_TOTAL)
#define DOFF_INVD_GC (DOFF_INVD_CC + NC_MAX)
#define DOFF_INVD_CG (DOFF_INVD_GC + NC_MAX)
#define DOFF_DESC    (DOFF_INVD_CG + NG_MAX)
#define DEG_TOTAL    (DOFF_DESC + 256)

__device__ float g_deg[DEG_TOTAL];

// Int scratch
#define IOFF_RP_CC  0
#define IOFF_CUR_CC (IOFF_RP_CC + NC_MAX + 1)
#define IOFF_RP_GC  (IOFF_CUR_CC + NC_MAX)
#define IOFF_CUR_GC (IOFF_RP_GC + NC_MAX + 1)
#define IOFF_RP_CG  (IOFF_CUR_GC + NC_MAX)
#define IOFF_CUR_CG (IOFF_RP_CG + NG_MAX + 1)
#define IOFF_COL_CC (IOFF_CUR_CG + NG_MAX)
#define IOFF_COL_GC (IOFF_COL_CC + ECC_MAX)
#define IOFF_COL_CG (IOFF_COL_GC + EGC_MAX)
#define INT_TOTAL   (IOFF_COL_CG + ECG_MAX)

__device__ int g_int[INT_TOTAL];

// ---------------------------------------------------------------------------
// Degree histogram: all 3 relations in one launch
// ---------------------------------------------------------------------------
__global__ void deg_all(const int* __restrict__ s0, const int* __restrict__ d0, int n0,
                        float* dS0, float* dD0,
                        const int* __restrict__ s1, const int* __restrict__ d1, int n1,
                        float* dS1, float* dD1,
                        const int* __restrict__ s2, const int* __restrict__ d2, int n2,
                        float* dS2, float* dD2) {
    int i = blockIdx.x * blockDim.x + threadIdx.x;
    if (i < n0) {
        atomicAdd(&dS0[s0[i]], 1.0f);
        atomicAdd(&dD0[d0[i]], 1.0f);
    } else if (i < n0 + n1) {
        int j = i - n0;
        atomicAdd(&dS1[s1[j]], 1.0f);
        atomicAdd(&dD1[d1[j]], 1.0f);
    } else if (i < n0 + n1 + n2) {
        int j = i - n0 - n1;
        atomicAdd(&dS2[s2[j]], 1.0f);
        atomicAdd(&dD2[d2[j]], 1.0f);
    }
}

// ---------------------------------------------------------------------------
// Single-kernel decoupled-lookback exclusive scan over 3 relations (+rsqrt).
// ---------------------------------------------------------------------------
#define SCAN_TILE 1024
#define SFLAG_A (1 << 30)
#define SFLAG_P (2 << 30)
#define SVALM   0x3FFFFFFF

__global__ __launch_bounds__(256) void scan_fused(
    float* c0, int n0, int* rp0, int* cur0,
    float* c1, int n1, int* rp1, int* cur1,
    float* c2, int n2, int* rp2, int* cur2,
    int nb0, int nb1, int nbT, int* desc,
    float* invs_region, int invs_n) {
    int gb = blockIdx.x;
    if (gb >= nbT) {
        int base = (gb - nbT) * SCAN_TILE + threadIdx.x * 4;
#pragma unroll
        for (int j = 0; j < 4; j++) {
            int i = base + j;
            if (i < invs_n) invs_region[i] = rsqrtf(fmaxf(invs_region[i], 1.0f));
        }
        return;
    }
    float* cnt; int n, lb, dbase, nbRel; int* rp; int* cur;
    if (gb < nb0) { cnt = c0; n = n0; lb = gb; dbase = 0; nbRel = nb0; rp = rp0; cur = cur0; }
    else if (gb < nb0 + nb1) { cnt = c1; n = n1; lb = gb - nb0; dbase = nb0; nbRel = nb1; rp = rp1; cur = cur1; }
    else { cnt = c2; n = n2; lb = gb - nb0 - nb1; dbase = nb0 + nb1; nbRel = nbT - nb0 - nb1; rp = rp2; cur = cur2; }

    int tid = threadIdx.x, lane = tid & 31, w = tid >> 5;
    int base = lb * SCAN_TILE + tid * 4;
    int v[4];
    int s = 0;
#pragma unroll
    for (int j = 0; j < 4; j++) {
        int i = base + j;
        v[j] = (i < n) ? (int)cnt[i] : 0;
        s += v[j];
    }
    int x = s;
#pragma unroll
    for (int o = 1; o < 32; o <<= 1) {
        int y = __shfl_up_sync(0xffffffffu, x, o);
        if (lane >= o) x += y;
    }
    __shared__ int ws[8];
    __shared__ int s_run;
    if (lane == 31) ws[w] = x;
    __syncthreads();

    if (w == 0) {
        int wv = (lane < 8) ? ws[lane] : 0;
        int wx = wv;
#pragma unroll
        for (int o = 1; o < 8; o <<= 1) {
            int y = __shfl_up_sync(0xffffffffu, wx, o);
            if (lane >= o) wx += y;
        }
        if (lane < 8) ws[lane] = wx - wv;
        int tot = __shfl_sync(0xffffffffu, wx, 7);

        int running = 0;
        if (lb > 0) {
            if (lane == 0) atomicExch(&desc[dbase + lb], SFLAG_A | tot);
            int j = lb - 1;
            while (true) {
                int idx = j - lane;
                int p = 0;
                if (idx >= 0) {
                    volatile int* dp = (volatile int*)(desc + dbase + idx);
                    do { p = *dp; } while ((p & (SFLAG_A | SFLAG_P)) == 0);
                }
                unsigned pm = __ballot_sync(0xffffffffu, idx >= 0 && (p & SFLAG_P));
                int contrib;
                if (pm) {
                    int firstP = __ffs(pm) - 1;
                    contrib = (idx >= 0 && lane <= firstP) ? (p & SVALM) : 0;
                } else {
                    contrib = (idx >= 0) ? (p & SVALM) : 0;
                }
#pragma unroll
                for (int o = 16; o; o >>= 1) contrib += __shfl_down_sync(0xffffffffu, contrib, o);
                contrib = __shfl_sync(0xffffffffu, contrib, 0);
                running += contrib;
                if (pm) break;
                j -= 32;
            }
        }
        if (lane == 0) {
            atomicExch(&desc[dbase + lb], SFLAG_P | (running + tot));
            s_run = running;
            if (lb == nbRel - 1) rp[n] = running + tot;
        }
    }
    __syncthreads();

    int excl = s_run + ws[w] + (x - s);
#pragma unroll
    for (int j = 0; j < 4; j++) {
        int i = base + j;
        if (i < n) {
            rp[i] = excl;
            cur[i] = excl;
            cnt[i] = rsqrtf(fmaxf((float)v[j], 1.0f));
        }
        excl += v[j];
    }
}

// CSR fill: all 3 relations in one launch (R7 form: one edge per thread)
__global__ void fill_all(const int* __restrict__ s0, const int* __restrict__ d0, int n0,
                         int* cur0, int* col0,
                         const int* __restrict__ s1, const int* __restrict__ d1, int n1,
                         int* cur1, int* col1,
                         const int* __restrict__ s2, const int* __restrict__ d2, int n2,
                         int* cur2, int* col2) {
    int i = blockIdx.x * blockDim.x + threadIdx.x;
    if (i < n0) {
        int p = atomicAdd(&cur0[d0[i]], 1);
        col0[p] = s0[i];
    } else if (i < n0 + n1) {
        int j = i - n0;
        int p = atomicAdd(&cur1[d1[j]], 1);
        col1[p] = s1[j];
    } else if (i < n0 + n1 + n2) {
        int j = i - n0 - n1;
        int p = atomicAdd(&cur2[d2[j]], 1);
        col2[p] = s2[j];
    }
}

// ---------------------------------------------------------------------------
// FP16 tensor-core GEMM (m16n8k16), 3 segments per grid, templated input type.
// (BYTE-EXACT R7 configuration, measured 31.9-32.6us / regs=126.)
// ---------------------------------------------------------------------------
#define KC 32

template <int IN_HALF>
__global__ __launch_bounds__(256) void sgemm_h16_3(
    const void* A0, const float* B0, const float* s0, __half* C0, int M0, int nb0,
    const void* A1, const float* B1, const float* s1, __half* C1, int M1, int nb1,
    const void* A2, const float* B2, const float* s2, __half* C2, int M2) {
    __shared__ __half As[2][128][40];
    __shared__ __half2 Bs2[2][KC / 2][136];

    const void* A;
    const float *B, *rowscale;
    __half* C;
    int M, lbk;
    int b = blockIdx.x;
    if (b < nb0) { A = A0; B = B0; rowscale = s0; C = C0; M = M0; lbk = b; }
    else if (b < nb0 + nb1) { A = A1; B = B1; rowscale = s1; C = C1; M = M1; lbk = b - nb0; }
    else { A = A2; B = B2; rowscale = s2; C = C2; M = M2; lbk = b - nb0 - nb1; }

    int tid = threadIdx.x;
    int warp = tid >> 5, lane = tid & 31;
    int wm = (warp >> 1) * 32;
    int wn = (warp & 1) * 64;
    int g = lane >> 2;
    int t = lane & 3;
    int block_row = lbk * 128;

    float acc[2][8][4];
#pragma unroll
    for (int i = 0; i < 2; i++)
#pragma unroll
        for (int j = 0; j < 8; j++)
#pragma unroll
            for (int k = 0; k < 4; k++) acc[i][j][k] = 0.0f;

    int ar = tid >> 3;
    int ac = (tid & 7) * 4;
    int kp = tid >> 5;
    int bn = (tid & 31) * 4;

    float4 aReg[4];
    uint2 aRegH[4];
    float4 bRegLo[2], bRegHi[2];

    // ---- load + store chunk 0 ----
#pragma unroll
    for (int i = 0; i < 4; i++) {
        int gr = block_row + ar + 32 * i;
        if (IN_HALF) {
            aRegH[i] = make_uint2(0u, 0u);
            if (gr < M) aRegH[i] = *(const uint2*)((const __half*)A + (size_t)gr * 128 + ac);
        } else {
            aReg[i] = make_float4(0.f, 0.f, 0.f, 0.f);
            if (gr < M) aReg[i] = *(const float4*)((const float*)A + (size_t)gr * 128 + ac);
        }
    }
#pragma unroll
    for (int i = 0; i < 2; i++) {
        int k = 2 * (kp + 8 * i);
        bRegLo[i] = *(const float4*)(B + (size_t)k * 128 + bn);
        bRegHi[i] = *(const float4*)(B + (size_t)(k + 1) * 128 + bn);
    }
#pragma unroll
    for (int i = 0; i < 4; i++) {
        int r = ar + 32 * i;
        __half2 h0, h1;
        if (IN_HALF) { h0 = *(__half2*)&aRegH[i].x; h1 = *(__half2*)&aRegH[i].y; }
        else { h0 = __floats2half2_rn(aReg[i].x, aReg[i].y); h1 = __floats2half2_rn(aReg[i].z, aReg[i].w); }
        *(__half2*)&As[0][r][ac + 0] = h0;
        *(__half2*)&As[0][r][ac + 2] = h1;
    }
#pragma unroll
    for (int i = 0; i < 2; i++) {
        int p = kp + 8 * i;
        Bs2[0][p][bn + 0] = __floats2half2_rn(bRegLo[i].x, bRegHi[i].x);
        Bs2[0][p][bn + 1] = __floats2half2_rn(bRegLo[i].y, bRegHi[i].y);
        Bs2[0][p][bn + 2] = __floats2half2_rn(bRegLo[i].z, bRegHi[i].z);
        Bs2[0][p][bn + 3] = __floats2half2_rn(bRegLo[i].w, bRegHi[i].w);
    }
    __syncthreads();

    int st = 0;
    for (int k0 = 0; k0 < 128; k0 += KC, st ^= 1) {
        bool hasNext = (k0 + KC < 128);
        // prefetch next chunk into regs
        if (hasNext) {
#pragma unroll
            for (int i = 0; i < 4; i++) {
                int gr = block_row + ar + 32 * i;
                if (gr < M) {
                    if (IN_HALF)
                        aRegH[i] = *(const uint2*)((const __half*)A + (size_t)gr * 128 + k0 + KC + ac);
                    else
                        aReg[i] = *(const float4*)((const float*)A + (size_t)gr * 128 + k0 + KC + ac);
                }
            }
#pragma unroll
            for (int i = 0; i < 2; i++) {
                int k = k0 + KC + 2 * (kp + 8 * i);
                bRegLo[i] = *(const float4*)(B + (size_t)k * 128 + bn);
                bRegHi[i] = *(const float4*)(B + (size_t)(k + 1) * 128 + bn);
            }
        }

        // mma over current stage
#pragma unroll
        for (int kk = 0; kk < KC; kk += 16) {
            uint32_t af[2][4];
#pragma unroll
            for (int ti = 0; ti < 2; ti++) {
                int row = wm + 16 * ti + g;
                int col = kk + 2 * t;
                af[ti][0] = *(const uint32_t*)&As[st][row][col];
                af[ti][1] = *(const uint32_t*)&As[st][row + 8][col];
                af[ti][2] = *(const uint32_t*)&As[st][row][col + 8];
                af[ti][3] = *(const uint32_t*)&As[st][row + 8][col + 8];
            }
            uint32_t bf[8][2];
#pragma unroll
            for (int u = 0; u < 8; u++) {
                int n = wn + 8 * u + g;
                int pb = (kk >> 1) + t;
                bf[u][0] = *(const uint32_t*)&Bs2[st][pb][n];
                bf[u][1] = *(const uint32_t*)&Bs2[st][pb + 4][n];
            }
#pragma unroll
            for (int ti = 0; ti < 2; ti++)
#pragma unroll
                for (int u = 0; u < 8; u++) {
                    asm volatile(
                        "mma.sync.aligned.m16n8k16.row.col.f32.f16.f16.f32 "
                        "{%0,%1,%2,%3}, {%4,%5,%6,%7}, {%8,%9}, {%0,%1,%2,%3};\n"
                        : "+f"(acc[ti][u][0]), "+f"(acc[ti][u][1]),
                          "+f"(acc[ti][u][2]), "+f"(acc[ti][u][3])
                        : "r"(af[ti][0]), "r"(af[ti][1]), "r"(af[ti][2]), "r"(af[ti][3]),
                          "r"(bf[u][0]), "r"(bf[u][1]));
                }
        }

        // store next chunk into other stage, then single sync
        if (hasNext) {
#pragma unroll
            for (int i = 0; i < 4; i++) {
                int r = ar + 32 * i;
                __half2 h0, h1;
                if (IN_HALF) { h0 = *(__half2*)&aRegH[i].x; h1 = *(__half2*)&aRegH[i].y; }
                else { h0 = __floats2half2_rn(aReg[i].x, aReg[i].y); h1 = __floats2half2_rn(aReg[i].z, aReg[i].w); }
                *(__half2*)&As[st ^ 1][r][ac + 0] = h0;
                *(__half2*)&As[st ^ 1][r][ac + 2] = h1;
            }
#pragma unroll
            for (int i = 0; i < 2; i++) {
                int p = kp + 8 * i;
                Bs2[st ^ 1][p][bn + 0] = __floats2half2_rn(bRegLo[i].x, bRegHi[i].x);
                Bs2[st ^ 1][p][bn + 1] = __floats2half2_rn(bRegLo[i].y, bRegHi[i].y);
                Bs2[st ^ 1][p][bn + 2] = __floats2half2_rn(bRegLo[i].z, bRegHi[i].z);
                Bs2[st ^ 1][p][bn + 3] = __floats2half2_rn(bRegLo[i].w, bRegHi[i].w);
            }
            __syncthreads();
        }
    }

#pragma unroll
    for (int ti = 0; ti < 2; ti++) {
        int row0 = block_row + wm + 16 * ti + g;
        int row1 = row0 + 8;
        float sc0 = (row0 < M) ? rowscale[row0] : 0.f;
        float sc1 = (row1 < M) ? rowscale[row1] : 0.f;
#pragma unroll
        for (int u = 0; u < 8; u++) {
            int cb = wn + 8 * u + 2 * t;
            if (row0 < M)
                *(__half2*)(C + (size_t)row0 * 128 + cb) =
                    __floats2half2_rn(acc[ti][u][0] * sc0, acc[ti][u][1] * sc0);
            if (row1 < M)
                *(__half2*)(C + (size_t)row1 * 128 + cb) =
                    __floats2half2_rn(acc[ti][u][2] * sc1, acc[ti][u][3] * sc1);
        }
    }
}

// ---------------------------------------------------------------------------
// Gather: CSR row sum over fp16 features. 4-edge MLP unroll with ONE level of
// fp16 pairwise adds (HADD2) before fp32 accumulation — halves cvt count and
// fp32 adds in the inner loop (gather is issue-bound per R11 ncu).
// ---------------------------------------------------------------------------
__device__ __forceinline__ void csr_rowsum_h(const int* __restrict__ rp,
                                             const int* __restrict__ col,
                                             const __half* __restrict__ feat,
                                             int r, int lo, float4& acc) {
    acc = make_float4(0.f, 0.f, 0.f, 0.f);
    int j = rp[r], e = rp[r + 1];
    for (; j + 3 < e; j += 4) {
        int s0 = col[j], s1 = col[j + 1], s2 = col[j + 2], s3 = col[j + 3];
        uint2 u0 = *(const uint2*)(feat + (size_t)s0 * FD + lo);
        uint2 u1 = *(const uint2*)(feat + (size_t)s1 * FD + lo);
        uint2 u2 = *(const uint2*)(feat + (size_t)s2 * FD + lo);
        uint2 u3 = *(const uint2*)(feat + (size_t)s3 * FD + lo);
        // one fp16 pairwise level: (v0+v1), (v2+v3)
        __half2 p0 = __hadd2(*(__half2*)&u0.x, *(__half2*)&u1.x);
        __half2 p1 = __hadd2(*(__half2*)&u0.y, *(__half2*)&u1.y);
        __half2 q0 = __hadd2(*(__half2*)&u2.x, *(__half2*)&u3.x);
        __half2 q1 = __hadd2(*(__half2*)&u2.y, *(__half2*)&u3.y);
        float2 f0 = __half22float2(p0), f1 = __half22float2(p1);
        float2 g0 = __half22float2(q0), g1 = __half22float2(q1);
        acc.x += f0.x + g0.x;
        acc.y += f0.y + g0.y;
        acc.z += f1.x + g1.x;
        acc.w += f1.y + g1.y;
    }
    for (; j < e; j++) {
        int s0 = col[j];
        uint2 u0 = *(const uint2*)(feat + (size_t)s0 * FD + lo);
        float2 a0 = __half22float2(*(__half2*)&u0.x), b0 = __half22float2(*(__half2*)&u0.y);
        acc.x += a0.x; acc.y += a0.y; acc.z += b0.x; acc.w += b0.y;
    }
}

__global__ __launch_bounds__(256) void gather_l1(
    const int* __restrict__ rpA, const int* __restrict__ colA,
    const __half* __restrict__ featA, const float* __restrict__ invdA,
    const float* __restrict__ bA,
    const int* __restrict__ rpB, const int* __restrict__ colB,
    const __half* __restrict__ featB, const float* __restrict__ invdB,
    const float* __restrict__ bB,
    __half* __restrict__ outC, int Nc,
    const int* __restrict__ rpG, const int* __restrict__ colG,
    const __half* __restrict__ featG, const float* __restrict__ invdG,
    const float* __restrict__ bG,
    __half* __restrict__ outG, int Ng) {
    int r = blockIdx.x * 8 + (threadIdx.x >> 5);
    int lane = threadIdx.x & 31;
    int lo = lane * 4;
    float4 res;
    __half* optr;
    if (r < Nc) {
        float4 a, b;
        csr_rowsum_h(rpA, colA, featA, r, lo, a);
        csr_rowsum_h(rpB, colB, featB, r, lo, b);
        float wa = invdA[r], wb = invdB[r];
        float4 ba = *(const float4*)(bA + lo);
        float4 bb = *(const float4*)(bB + lo);
        res = make_float4(a.x * wa + b.x * wb + ba.x + bb.x,
                          a.y * wa + b.y * wb + ba.y + bb.y,
                          a.z * wa + b.z * wb + ba.z + bb.z,
                          a.w * wa + b.w * wb + ba.w + bb.w);
        optr = outC + (size_t)r * FD + lo;
    } else if (r < Nc + Ng) {
        int rg = r - Nc;
        float4 a;
        csr_rowsum_h(rpG, colG, featG, rg, lo, a);
        float w = invdG[rg];
        float4 bb = *(const float4*)(bG + lo);
        res = make_float4(a.x * w + bb.x, a.y * w + bb.y,
                          a.z * w + bb.z, a.w * w + bb.w);
        optr = outG + (size_t)rg * FD + lo;
    } else {
        return;
    }
    res.x = res.x > 0.f ? res.x : 0.01f * res.x;
    res.y = res.y > 0.f ? res.y : 0.01f * res.y;
    res.z = res.z > 0.f ? res.z : 0.01f * res.z;
    res.w = res.w > 0.f ? res.w : 0.01f * res.w;
    *(__half2*)(optr + 0) = __floats2half2_rn(res.x, res.y);
    *(__half2*)(optr + 2) = __floats2half2_rn(res.z, res.w);
}

__global__ __launch_bounds__(256) void gather_l2(
    const int* __restrict__ rpA, const int* __restrict__ colA,
    const __half* __restrict__ featA, const float* __restrict__ invdA,
    const float* __restrict__ bA,
    const int* __restrict__ rpB, const int* __restrict__ colB,
    const __half* __restrict__ featB, const float* __restrict__ invdB,
    const float* __restrict__ bB,
    float* __restrict__ out, int rows) {
    int r = blockIdx.x * 8 + (threadIdx.x >> 5);
    if (r >= rows) return;
    int lane = threadIdx.x & 31;
    int lo = lane * 4;
    float4 a, b;
    csr_rowsum_h(rpA, colA, featA, r, lo, a);
    csr_rowsum_h(rpB, colB, featB, r, lo, b);
    float wa = invdA[r], wb = invdB[r];
    float4 ba = *(const float4*)(bA + lo);
    float4 bb = *(const float4*)(bB + lo);
    float4 res = make_float4(a.x * wa + b.x * wb + ba.x + bb.x,
                             a.y * wa + b.y * wb + ba.y + bb.y,
                             a.z * wa + b.z * wb + ba.z + bb.z,
                             a.w * wa + b.w * wb + ba.w + bb.w);
    *(float4*)(out + (size_t)r * FD + lo) = res;
}

// ---------------------------------------------------------------------------
// Host launch
// ---------------------------------------------------------------------------
extern "C" void kernel_launch(void* const* d_in, const int* in_sizes, int n_in,
                              void* d_out, int out_size) {
    const float* x_chem = (const float*)d_in[0];
    const float* x_gene = (const float*)d_in[1];
    const int* src_cc = (const int*)d_in[2];
    const int* dst_cc = (const int*)d_in[3];
    const int* src_cg = (const int*)d_in[4];
    const int* dst_cg = (const int*)d_in[5];
    const int* src_gc = (const int*)d_in[6];
    const int* dst_gc = (const int*)d_in[7];

    const float *W1_cc, *W1_cg, *W1_gc, *W2_cc, *W2_gc;
    const float *b1_cc, *b1_cg, *b1_gc, *b2_cc, *b2_gc;
    if (in_sizes[9] == FD) {  // interleaved
        W1_cc = (const float*)d_in[8];  b1_cc = (const float*)d_in[9];
        W1_cg = (const float*)d_in[10]; b1_cg = (const float*)d_in[11];
        W1_gc = (const float*)d_in[12]; b1_gc = (const float*)d_in[13];
        W2_cc = (const float*)d_in[14]; b2_cc = (const float*)d_in[15];
        W2_gc = (const float*)d_in[18]; b2_gc = (const float*)d_in[19];
    } else {                  // grouped
        W1_cc = (const float*)d_in[8];
        W1_cg = (const float*)d_in[9];
        W1_gc = (const float*)d_in[10];
        W2_cc = (const float*)d_in[11];
        W2_gc = (const float*)d_in[13];
        b1_cc = (const float*)d_in[14];
        b1_cg = (const float*)d_in[15];
        b1_gc = (const float*)d_in[16];
        b2_cc = (const float*)d_in[17];
        b2_gc = (const float*)d_in[19];
    }

    int Nc = in_sizes[0] / FD;
    int Ng = in_sizes[1] / FD;
    int nEcc = in_sizes[2];
    int nEcg = in_sizes[4];
    int nEgc = in_sizes[6];

    __half* hs = nullptr;
    float* deg = nullptr;
    int* ints = nullptr;
    cudaGetSymbolAddress((void**)&hs, g_hscratch);
    cudaGetSymbolAddress((void**)&deg, g_deg);
    cudaGetSymbolAddress((void**)&ints, g_int);

    __half* Ycc = hs + HOFF_YCC;
    __half* Ycg = hs + HOFF_YCG;
    __half* Ygc = hs + HOFF_YGC;
    __half* h1c = hs + HOFF_H1C;
    __half* h1g = hs + HOFF_H1G;

    float* invs_cc = deg + DOFF_INVS_CC;
    float* invs_cg = deg + DOFF_INVS_CG;
    float* invs_gc = deg + DOFF_INVS_GC;
    float* invd_cc = deg + DOFF_INVD_CC;
    float* invd_gc = deg + DOFF_INVD_GC;
    float* invd_cg = deg + DOFF_INVD_CG;
    int* desc = (int*)(deg + DOFF_DESC);

    int* rp_cc = ints + IOFF_RP_CC;
    int* cur_cc = ints + IOFF_CUR_CC;
    int* rp_gc = ints + IOFF_RP_GC;
    int* cur_gc = ints + IOFF_CUR_GC;
    int* rp_cg = ints + IOFF_RP_CG;
    int* cur_cg = ints + IOFF_CUR_CG;
    int* col_cc = ints + IOFF_COL_CC;
    int* col_gc = ints + IOFF_COL_GC;
    int* col_cg = ints + IOFF_COL_CG;

    float* out = (float*)d_out;

    // ---- zero degrees + scan descriptors ----
    cudaMemsetAsync(deg, 0, DEG_TOTAL * sizeof(float), 0);

    // ---- degree histograms ----
    int nEtot = nEcc + nEcg + nEgc;
    deg_all<<<(nEtot + 255) / 256, 256>>>(src_cc, dst_cc, nEcc, invs_cc, invd_cc,
                                          src_cg, dst_cg, nEcg, invs_cg, invd_cg,
                                          src_gc, dst_gc, nEgc, invs_gc, invd_gc);

    // ---- single-kernel decoupled-lookback scan (+ fused rsqrt) ----
    int nb0 = (Nc + SCAN_TILE - 1) / SCAN_TILE;
    int nb1 = (Nc + SCAN_TILE - 1) / SCAN_TILE;
    int nb2 = (Ng + SCAN_TILE - 1) / SCAN_TILE;
    int nbT = nb0 + nb1 + nb2;
    int nrs = (INVS_TOTAL + SCAN_TILE - 1) / SCAN_TILE;
    scan_fused<<<nbT + nrs, 256>>>(invd_cc, Nc, rp_cc, cur_cc,
                                   invd_gc, Nc, rp_gc, cur_gc,
                                   invd_cg, Ng, rp_cg, cur_cg,
                                   nb0, nb1, nbT, desc,
                                   deg, INVS_TOTAL);
    fill_all<<<(nEtot + 255) / 256, 256>>>(src_cc, dst_cc, nEcc, cur_cc, col_cc,
                                           src_gc, dst_gc, nEgc, cur_gc, col_gc,
                                           src_cg, dst_cg, nEcg, cur_cg, col_cg);

    // ---- layer 1: all three GEMMs in one grid (fp32 in -> fp16 mma -> fp16 out) ----
    int gBlkC = (Nc + 127) / 128;
    int gBlkG = (Ng + 127) / 128;
    sgemm_h16_3<0><<<2 * gBlkC + gBlkG, 256>>>(
        x_chem, W1_cc, invs_cc, Ycc, Nc, gBlkC,
        x_chem, W1_cg, invs_cg, Ycg, Nc, gBlkC,
        x_gene, W1_gc, invs_gc, Ygc, Ng);

    // ---- layer 1: fused gathers ----
    gather_l1<<<(Nc + Ng + 7) / 8, 256>>>(rp_cc, col_cc, Ycc, invd_cc, b1_cc,
                                          rp_gc, col_gc, Ygc, invd_gc, b1_gc,
                                          h1c, Nc,
                                          rp_cg, col_cg, Ycg, invd_cg, b1_cg,
                                          h1g, Ng);

    // ---- layer 2: both GEMMs in one grid (fp16 in, fp16 out) ----
    sgemm_h16_3<1><<<gBlkC + gBlkG, 256>>>(
        h1c, W2_cc, invs_cc, Ycc, Nc, gBlkC,
        h1g, W2_gc, invs_gc, Ygc, Ng, gBlkG,
        (const void*)nullptr, (const float*)nullptr, (const float*)nullptr,
        (__half*)nullptr, 0);

    // ---- layer 2: gather -> fp32 output ----
    gather_l2<<<(Nc + 7) / 8, 256>>>(rp_cc, col_cc, Ycc, invd_cc, b2_cc,
                                     rp_gc, col_gc, Ygc, invd_gc, b2_gc,
                                     out, Nc);
}

// round 17
// speedup vs baseline: 1.0175x; 1.0175x over previous
#include <cuda_runtime.h>
#include <cuda_fp16.h>
#include <cstdint>

// ---------------------------------------------------------------------------
// Problem constants
// ---------------------------------------------------------------------------
#define NC_MAX 50000
#define NG_MAX 30000
#define FD 128
#define ECC_MAX 500000
#define ECG_MAX 400000
#define EGC_MAX 400000

// fp16 feature scratch
#define HOFF_YCC ((size_t)0)
#define HOFF_YCG ((size_t)NC_MAX * FD)
#define HOFF_YGC ((size_t)2 * NC_MAX * FD)
#define HOFF_H1C (HOFF_YGC + (size_t)NG_MAX * FD)
#define HOFF_H1G (HOFF_H1C + (size_t)NC_MAX * FD)
#define HSCRATCH_TOTAL (HOFF_H1G + (size_t)NG_MAX * FD)

__device__ __align__(16) __half g_hscratch[HSCRATCH_TOTAL];

// Degree arrays. Layout: [invs_cc | invs_cg | invs_gc | invd_cc | invd_gc | invd_cg | desc]
#define DOFF_INVS_CC 0
#define DOFF_INVS_CG (DOFF_INVS_CC + NC_MAX)
#define DOFF_INVS_GC (DOFF_INVS_CG + NC_MAX)
#define INVS_TOTAL   (DOFF_INVS_GC + NG_MAX)
#define DOFF_INVD_CC (INVS_TOTAL)
#define DOFF_INVD_GC (DOFF_INVD_CC + NC_MAX)
#define DOFF_INVD_CG (DOFF_INVD_GC + NC_MAX)
#define DOFF_DESC    (DOFF_INVD_CG + NG_MAX)
#define DEG_TOTAL    (DOFF_DESC + 256)

__device__ float g_deg[DEG_TOTAL];

// Int scratch
#define IOFF_RP_CC  0
#define IOFF_CUR_CC (IOFF_RP_CC + NC_MAX + 1)
#define IOFF_RP_GC  (IOFF_CUR_CC + NC_MAX)
#define IOFF_CUR_GC (IOFF_RP_GC + NC_MAX + 1)
#define IOFF_RP_CG  (IOFF_CUR_GC + NC_MAX)
#define IOFF_CUR_CG (IOFF_RP_CG + NG_MAX + 1)
#define IOFF_COL_CC (IOFF_CUR_CG + NG_MAX)
#define IOFF_COL_GC (IOFF_COL_CC + ECC_MAX)
#define IOFF_COL_CG (IOFF_COL_GC + EGC_MAX)
#define INT_TOTAL   (IOFF_COL_CG + ECG_MAX)

__device__ int g_int[INT_TOTAL];

// ---------------------------------------------------------------------------
// Degree histogram: all 3 relations in one launch
// ---------------------------------------------------------------------------
__global__ void deg_all(const int* __restrict__ s0, const int* __restrict__ d0, int n0,
                        float* dS0, float* dD0,
                        const int* __restrict__ s1, const int* __restrict__ d1, int n1,
                        float* dS1, float* dD1,
                        const int* __restrict__ s2, const int* __restrict__ d2, int n2,
                        float* dS2, float* dD2) {
    int i = blockIdx.x * blockDim.x + threadIdx.x;
    if (i < n0) {
        atomicAdd(&dS0[s0[i]], 1.0f);
        atomicAdd(&dD0[d0[i]], 1.0f);
    } else if (i < n0 + n1) {
        int j = i - n0;
        atomicAdd(&dS1[s1[j]], 1.0f);
        atomicAdd(&dD1[d1[j]], 1.0f);
    } else if (i < n0 + n1 + n2) {
        int j = i - n0 - n1;
        atomicAdd(&dS2[s2[j]], 1.0f);
        atomicAdd(&dD2[d2[j]], 1.0f);
    }
}

// ---------------------------------------------------------------------------
// Single-kernel decoupled-lookback exclusive scan over 3 relations (+rsqrt).
// ---------------------------------------------------------------------------
#define SCAN_TILE 1024
#define SFLAG_A (1 << 30)
#define SFLAG_P (2 << 30)
#define SVALM   0x3FFFFFFF

__global__ __launch_bounds__(256) void scan_fused(
    float* c0, int n0, int* rp0, int* cur0,
    float* c1, int n1, int* rp1, int* cur1,
    float* c2, int n2, int* rp2, int* cur2,
    int nb0, int nb1, int nbT, int* desc,
    float* invs_region, int invs_n) {
    int gb = blockIdx.x;
    if (gb >= nbT) {
        int base = (gb - nbT) * SCAN_TILE + threadIdx.x * 4;
#pragma unroll
        for (int j = 0; j < 4; j++) {
            int i = base + j;
            if (i < invs_n) invs_region[i] = rsqrtf(fmaxf(invs_region[i], 1.0f));
        }
        return;
    }
    float* cnt; int n, lb, dbase, nbRel; int* rp; int* cur;
    if (gb < nb0) { cnt = c0; n = n0; lb = gb; dbase = 0; nbRel = nb0; rp = rp0; cur = cur0; }
    else if (gb < nb0 + nb1) { cnt = c1; n = n1; lb = gb - nb0; dbase = nb0; nbRel = nb1; rp = rp1; cur = cur1; }
    else { cnt = c2; n = n2; lb = gb - nb0 - nb1; dbase = nb0 + nb1; nbRel = nbT - nb0 - nb1; rp = rp2; cur = cur2; }

    int tid = threadIdx.x, lane = tid & 31, w = tid >> 5;
    int base = lb * SCAN_TILE + tid * 4;
    int v[4];
    int s = 0;
#pragma unroll
    for (int j = 0; j < 4; j++) {
        int i = base + j;
        v[j] = (i < n) ? (int)cnt[i] : 0;
        s += v[j];
    }
    int x = s;
#pragma unroll
    for (int o = 1; o < 32; o <<= 1) {
        int y = __shfl_up_sync(0xffffffffu, x, o);
        if (lane >= o) x += y;
    }
    __shared__ int ws[8];
    __shared__ int s_run;
    if (lane == 31) ws[w] = x;
    __syncthreads();

    if (w == 0) {
        int wv = (lane < 8) ? ws[lane] : 0;
        int wx = wv;
#pragma unroll
        for (int o = 1; o < 8; o <<= 1) {
            int y = __shfl_up_sync(0xffffffffu, wx, o);
            if (lane >= o) wx += y;
        }
        if (lane < 8) ws[lane] = wx - wv;
        int tot = __shfl_sync(0xffffffffu, wx, 7);

        int running = 0;
        if (lb > 0) {
            if (lane == 0) atomicExch(&desc[dbase + lb], SFLAG_A | tot);
            int j = lb - 1;
            while (true) {
                int idx = j - lane;
                int p = 0;
                if (idx >= 0) {
                    volatile int* dp = (volatile int*)(desc + dbase + idx);
                    do { p = *dp; } while ((p & (SFLAG_A | SFLAG_P)) == 0);
                }
                unsigned pm = __ballot_sync(0xffffffffu, idx >= 0 && (p & SFLAG_P));
                int contrib;
                if (pm) {
                    int firstP = __ffs(pm) - 1;
                    contrib = (idx >= 0 && lane <= firstP) ? (p & SVALM) : 0;
                } else {
                    contrib = (idx >= 0) ? (p & SVALM) : 0;
                }
#pragma unroll
                for (int o = 16; o; o >>= 1) contrib += __shfl_down_sync(0xffffffffu, contrib, o);
                contrib = __shfl_sync(0xffffffffu, contrib, 0);
                running += contrib;
                if (pm) break;
                j -= 32;
            }
        }
        if (lane == 0) {
            atomicExch(&desc[dbase + lb], SFLAG_P | (running + tot));
            s_run = running;
            if (lb == nbRel - 1) rp[n] = running + tot;
        }
    }
    __syncthreads();

    int excl = s_run + ws[w] + (x - s);
#pragma unroll
    for (int j = 0; j < 4; j++) {
        int i = base + j;
        if (i < n) {
            rp[i] = excl;
            cur[i] = excl;
            cnt[i] = rsqrtf(fmaxf((float)v[j], 1.0f));
        }
        excl += v[j];
    }
}

// CSR fill: all 3 relations in one launch (R7 form: one edge per thread)
__global__ void fill_all(const int* __restrict__ s0, const int* __restrict__ d0, int n0,
                         int* cur0, int* col0,
                         const int* __restrict__ s1, const int* __restrict__ d1, int n1,
                         int* cur1, int* col1,
                         const int* __restrict__ s2, const int* __restrict__ d2, int n2,
                         int* cur2, int* col2) {
    int i = blockIdx.x * blockDim.x + threadIdx.x;
    if (i < n0) {
        int p = atomicAdd(&cur0[d0[i]], 1);
        col0[p] = s0[i];
    } else if (i < n0 + n1) {
        int j = i - n0;
        int p = atomicAdd(&cur1[d1[j]], 1);
        col1[p] = s1[j];
    } else if (i < n0 + n1 + n2) {
        int j = i - n0 - n1;
        int p = atomicAdd(&cur2[d2[j]], 1);
        col2[p] = s2[j];
    }
}

// ---------------------------------------------------------------------------
// FP16 tensor-core GEMM (m16n8k16), 3 segments per grid, templated input type.
// C[M,128] = (A[M,128] @ B[128,128]) * rowscale[r]; C stored fp16.
// 256 threads = 8 warps (4m x 2n), warp tile 32x64, double-buffered smem,
// loop shape: prefetch regs -> mma(st) -> store(st^1) -> sync.
// (BYTE-EXACT R7/R15 configuration, measured 31.9-32.6us / regs=126.)
// ---------------------------------------------------------------------------
#define KC 32

template <int IN_HALF>
__global__ __launch_bounds__(256) void sgemm_h16_3(
    const void* A0, const float* B0, const float* s0, __half* C0, int M0, int nb0,
    const void* A1, const float* B1, const float* s1, __half* C1, int M1, int nb1,
    const void* A2, const float* B2, const float* s2, __half* C2, int M2) {
    __shared__ __half As[2][128][40];
    __shared__ __half2 Bs2[2][KC / 2][136];

    const void* A;
    const float *B, *rowscale;
    __half* C;
    int M, lbk;
    int b = blockIdx.x;
    if (b < nb0) { A = A0; B = B0; rowscale = s0; C = C0; M = M0; lbk = b; }
    else if (b < nb0 + nb1) { A = A1; B = B1; rowscale = s1; C = C1; M = M1; lbk = b - nb0; }
    else { A = A2; B = B2; rowscale = s2; C = C2; M = M2; lbk = b - nb0 - nb1; }

    int tid = threadIdx.x;
    int warp = tid >> 5, lane = tid & 31;
    int wm = (warp >> 1) * 32;
    int wn = (warp & 1) * 64;
    int g = lane >> 2;
    int t = lane & 3;
    int block_row = lbk * 128;

    float acc[2][8][4];
#pragma unroll
    for (int i = 0; i < 2; i++)
#pragma unroll
        for (int j = 0; j < 8; j++)
#pragma unroll
            for (int k = 0; k < 4; k++) acc[i][j][k] = 0.0f;

    int ar = tid >> 3;
    int ac = (tid & 7) * 4;
    int kp = tid >> 5;
    int bn = (tid & 31) * 4;

    float4 aReg[4];
    uint2 aRegH[4];
    float4 bRegLo[2], bRegHi[2];

    // ---- load + store chunk 0 ----
#pragma unroll
    for (int i = 0; i < 4; i++) {
        int gr = block_row + ar + 32 * i;
        if (IN_HALF) {
            aRegH[i] = make_uint2(0u, 0u);
            if (gr < M) aRegH[i] = *(const uint2*)((const __half*)A + (size_t)gr * 128 + ac);
        } else {
            aReg[i] = make_float4(0.f, 0.f, 0.f, 0.f);
            if (gr < M) aReg[i] = *(const float4*)((const float*)A + (size_t)gr * 128 + ac);
        }
    }
#pragma unroll
    for (int i = 0; i < 2; i++) {
        int k = 2 * (kp + 8 * i);
        bRegLo[i] = *(const float4*)(B + (size_t)k * 128 + bn);
        bRegHi[i] = *(const float4*)(B + (size_t)(k + 1) * 128 + bn);
    }
#pragma unroll
    for (int i = 0; i < 4; i++) {
        int r = ar + 32 * i;
        __half2 h0, h1;
        if (IN_HALF) { h0 = *(__half2*)&aRegH[i].x; h1 = *(__half2*)&aRegH[i].y; }
        else { h0 = __floats2half2_rn(aReg[i].x, aReg[i].y); h1 = __floats2half2_rn(aReg[i].z, aReg[i].w); }
        *(__half2*)&As[0][r][ac + 0] = h0;
        *(__half2*)&As[0][r][ac + 2] = h1;
    }
#pragma unroll
    for (int i = 0; i < 2; i++) {
        int p = kp + 8 * i;
        Bs2[0][p][bn + 0] = __floats2half2_rn(bRegLo[i].x, bRegHi[i].x);
        Bs2[0][p][bn + 1] = __floats2half2_rn(bRegLo[i].y, bRegHi[i].y);
        Bs2[0][p][bn + 2] = __floats2half2_rn(bRegLo[i].z, bRegHi[i].z);
        Bs2[0][p][bn + 3] = __floats2half2_rn(bRegLo[i].w, bRegHi[i].w);
    }
    __syncthreads();

    int st = 0;
    for (int k0 = 0; k0 < 128; k0 += KC, st ^= 1) {
        bool hasNext = (k0 + KC < 128);
        // prefetch next chunk into regs
        if (hasNext) {
#pragma unroll
            for (int i = 0; i < 4; i++) {
                int gr = block_row + ar + 32 * i;
                if (gr < M) {
                    if (IN_HALF)
                        aRegH[i] = *(const uint2*)((const __half*)A + (size_t)gr * 128 + k0 + KC + ac);
                    else
                        aReg[i] = *(const float4*)((const float*)A + (size_t)gr * 128 + k0 + KC + ac);
                }
            }
#pragma unroll
            for (int i = 0; i < 2; i++) {
                int k = k0 + KC + 2 * (kp + 8 * i);
                bRegLo[i] = *(const float4*)(B + (size_t)k * 128 + bn);
                bRegHi[i] = *(const float4*)(B + (size_t)(k + 1) * 128 + bn);
            }
        }

        // mma over current stage
#pragma unroll
        for (int kk = 0; kk < KC; kk += 16) {
            uint32_t af[2][4];
#pragma unroll
            for (int ti = 0; ti < 2; ti++) {
                int row = wm + 16 * ti + g;
                int col = kk + 2 * t;
                af[ti][0] = *(const uint32_t*)&As[st][row][col];
                af[ti][1] = *(const uint32_t*)&As[st][row + 8][col];
                af[ti][2] = *(const uint32_t*)&As[st][row][col + 8];
                af[ti][3] = *(const uint32_t*)&As[st][row + 8][col + 8];
            }
            uint32_t bf[8][2];
#pragma unroll
            for (int u = 0; u < 8; u++) {
                int n = wn + 8 * u + g;
                int pb = (kk >> 1) + t;
                bf[u][0] = *(const uint32_t*)&Bs2[st][pb][n];
                bf[u][1] = *(const uint32_t*)&Bs2[st][pb + 4][n];
            }
#pragma unroll
            for (int ti = 0; ti < 2; ti++)
#pragma unroll
                for (int u = 0; u < 8; u++) {
                    asm volatile(
                        "mma.sync.aligned.m16n8k16.row.col.f32.f16.f16.f32 "
                        "{%0,%1,%2,%3}, {%4,%5,%6,%7}, {%8,%9}, {%0,%1,%2,%3};\n"
                        : "+f"(acc[ti][u][0]), "+f"(acc[ti][u][1]),
                          "+f"(acc[ti][u][2]), "+f"(acc[ti][u][3])
                        : "r"(af[ti][0]), "r"(af[ti][1]), "r"(af[ti][2]), "r"(af[ti][3]),
                          "r"(bf[u][0]), "r"(bf[u][1]));
                }
        }

        // store next chunk into other stage, then single sync
        if (hasNext) {
#pragma unroll
            for (int i = 0; i < 4; i++) {
                int r = ar + 32 * i;
                __half2 h0, h1;
                if (IN_HALF) { h0 = *(__half2*)&aRegH[i].x; h1 = *(__half2*)&aRegH[i].y; }
                else { h0 = __floats2half2_rn(aReg[i].x, aReg[i].y); h1 = __floats2half2_rn(aReg[i].z, aReg[i].w); }
                *(__half2*)&As[st ^ 1][r][ac + 0] = h0;
                *(__half2*)&As[st ^ 1][r][ac + 2] = h1;
            }
#pragma unroll
            for (int i = 0; i < 2; i++) {
                int p = kp + 8 * i;
                Bs2[st ^ 1][p][bn + 0] = __floats2half2_rn(bRegLo[i].x, bRegHi[i].x);
                Bs2[st ^ 1][p][bn + 1] = __floats2half2_rn(bRegLo[i].y, bRegHi[i].y);
                Bs2[st ^ 1][p][bn + 2] = __floats2half2_rn(bRegLo[i].z, bRegHi[i].z);
                Bs2[st ^ 1][p][bn + 3] = __floats2half2_rn(bRegLo[i].w, bRegHi[i].w);
            }
            __syncthreads();
        }
    }

#pragma unroll
    for (int ti = 0; ti < 2; ti++) {
        int row0 = block_row + wm + 16 * ti + g;
        int row1 = row0 + 8;
        float sc0 = (row0 < M) ? rowscale[row0] : 0.f;
        float sc1 = (row1 < M) ? rowscale[row1] : 0.f;
#pragma unroll
        for (int u = 0; u < 8; u++) {
            int cb = wn + 8 * u + 2 * t;
            if (row0 < M)
                *(__half2*)(C + (size_t)row0 * 128 + cb) =
                    __floats2half2_rn(acc[ti][u][0] * sc0, acc[ti][u][1] * sc0);
            if (row1 < M)
                *(__half2*)(C + (size_t)row1 * 128 + cb) =
                    __floats2half2_rn(acc[ti][u][2] * sc1, acc[ti][u][3] * sc1);
        }
    }
}

// ---------------------------------------------------------------------------
// Gather: CSR row sum over fp16 features, fp32 accumulation, 4-edge MLP unroll
// (R15 form — verified best)
// ---------------------------------------------------------------------------
__device__ __forceinline__ void csr_rowsum_h(const int* __restrict__ rp,
                                             const int* __restrict__ col,
                                             const __half* __restrict__ feat,
                                             int r, int lo, float4& acc) {
    acc = make_float4(0.f, 0.f, 0.f, 0.f);
    int j = rp[r], e = rp[r + 1];
    for (; j + 3 < e; j += 4) {
        int s0 = col[j], s1 = col[j + 1], s2 = col[j + 2], s3 = col[j + 3];
        uint2 u0 = *(const uint2*)(feat + (size_t)s0 * FD + lo);
        uint2 u1 = *(const uint2*)(feat + (size_t)s1 * FD + lo);
        uint2 u2 = *(const uint2*)(feat + (size_t)s2 * FD + lo);
        uint2 u3 = *(const uint2*)(feat + (size_t)s3 * FD + lo);
        float2 a0 = __half22float2(*(__half2*)&u0.x), b0 = __half22float2(*(__half2*)&u0.y);
        float2 a1 = __half22float2(*(__half2*)&u1.x), b1 = __half22float2(*(__half2*)&u1.y);
        float2 a2 = __half22float2(*(__half2*)&u2.x), b2 = __half22float2(*(__half2*)&u2.y);
        float2 a3 = __half22float2(*(__half2*)&u3.x), b3 = __half22float2(*(__half2*)&u3.y);
        acc.x += (a0.x + a1.x) + (a2.x + a3.x);
        acc.y += (a0.y + a1.y) + (a2.y + a3.y);
        acc.z += (b0.x + b1.x) + (b2.x + b3.x);
        acc.w += (b0.y + b1.y) + (b2.y + b3.y);
    }
    for (; j < e; j++) {
        int s0 = col[j];
        uint2 u0 = *(const uint2*)(feat + (size_t)s0 * FD + lo);
        float2 a0 = __half22float2(*(__half2*)&u0.x), b0 = __half22float2(*(__half2*)&u0.y);
        acc.x += a0.x; acc.y += a0.y; acc.z += b0.x; acc.w += b0.y;
    }
}

__global__ __launch_bounds__(256) void gather_l1(
    const int* __restrict__ rpA, const int* __restrict__ colA,
    const __half* __restrict__ featA, const float* __restrict__ invdA,
    const float* __restrict__ bA,
    const int* __restrict__ rpB, const int* __restrict__ colB,
    const __half* __restrict__ featB, const float* __restrict__ invdB,
    const float* __restrict__ bB,
    __half* __restrict__ outC, int Nc,
    const int* __restrict__ rpG, const int* __restrict__ colG,
    const __half* __restrict__ featG, const float* __restrict__ invdG,
    const float* __restrict__ bG,
    __half* __restrict__ outG, int Ng) {
    int r = blockIdx.x * 8 + (threadIdx.x >> 5);
    int lane = threadIdx.x & 31;
    int lo = lane * 4;
    float4 res;
    __half* optr;
    if (r < Nc) {
        float4 a, b;
        csr_rowsum_h(rpA, colA, featA, r, lo, a);
        csr_rowsum_h(rpB, colB, featB, r, lo, b);
        float wa = invdA[r], wb = invdB[r];
        float4 ba = *(const float4*)(bA + lo);
        float4 bb = *(const float4*)(bB + lo);
        res = make_float4(a.x * wa + b.x * wb + ba.x + bb.x,
                          a.y * wa + b.y * wb + ba.y + bb.y,
                          a.z * wa + b.z * wb + ba.z + bb.z,
                          a.w * wa + b.w * wb + ba.w + bb.w);
        optr = outC + (size_t)r * FD + lo;
    } else if (r < Nc + Ng) {
        int rg = r - Nc;
        float4 a;
        csr_rowsum_h(rpG, colG, featG, rg, lo, a);
        float w = invdG[rg];
        float4 bb = *(const float4*)(bG + lo);
        res = make_float4(a.x * w + bb.x, a.y * w + bb.y,
                          a.z * w + bb.z, a.w * w + bb.w);
        optr = outG + (size_t)rg * FD + lo;
    } else {
        return;
    }
    res.x = res.x > 0.f ? res.x : 0.01f * res.x;
    res.y = res.y > 0.f ? res.y : 0.01f * res.y;
    res.z = res.z > 0.f ? res.z : 0.01f * res.z;
    res.w = res.w > 0.f ? res.w : 0.01f * res.w;
    *(__half2*)(optr + 0) = __floats2half2_rn(res.x, res.y);
    *(__half2*)(optr + 2) = __floats2half2_rn(res.z, res.w);
}

__global__ __launch_bounds__(256) void gather_l2(
    const int* __restrict__ rpA, const int* __restrict__ colA,
    const __half* __restrict__ featA, const float* __restrict__ invdA,
    const float* __restrict__ bA,
    const int* __restrict__ rpB, const int* __restrict__ colB,
    const __half* __restrict__ featB, const float* __restrict__ invdB,
    const float* __restrict__ bB,
    float* __restrict__ out, int rows) {
    int r = blockIdx.x * 8 + (threadIdx.x >> 5);
    if (r >= rows) return;
    int lane = threadIdx.x & 31;
    int lo = lane * 4;
    float4 a, b;
    csr_rowsum_h(rpA, colA, featA, r, lo, a);
    csr_rowsum_h(rpB, colB, featB, r, lo, b);
    float wa = invdA[r], wb = invdB[r];
    float4 ba = *(const float4*)(bA + lo);
    float4 bb = *(const float4*)(bB + lo);
    float4 res = make_float4(a.x * wa + b.x * wb + ba.x + bb.x,
                             a.y * wa + b.y * wb + ba.y + bb.y,
                             a.z * wa + b.z * wb + ba.z + bb.z,
                             a.w * wa + b.w * wb + ba.w + bb.w);
    *(float4*)(out + (size_t)r * FD + lo) = res;
}

// ---------------------------------------------------------------------------
// Host launch
// ---------------------------------------------------------------------------
extern "C" void kernel_launch(void* const* d_in, const int* in_sizes, int n_in,
                              void* d_out, int out_size) {
    const float* x_chem = (const float*)d_in[0];
    const float* x_gene = (const float*)d_in[1];
    const int* src_cc = (const int*)d_in[2];
    const int* dst_cc = (const int*)d_in[3];
    const int* src_cg = (const int*)d_in[4];
    const int* dst_cg = (const int*)d_in[5];
    const int* src_gc = (const int*)d_in[6];
    const int* dst_gc = (const int*)d_in[7];

    const float *W1_cc, *W1_cg, *W1_gc, *W2_cc, *W2_gc;
    const float *b1_cc, *b1_cg, *b1_gc, *b2_cc, *b2_gc;
    if (in_sizes[9] == FD) {  // interleaved
        W1_cc = (const float*)d_in[8];  b1_cc = (const float*)d_in[9];
        W1_cg = (const float*)d_in[10]; b1_cg = (const float*)d_in[11];
        W1_gc = (const float*)d_in[12]; b1_gc = (const float*)d_in[13];
        W2_cc = (const float*)d_in[14]; b2_cc = (const float*)d_in[15];
        W2_gc = (const float*)d_in[18]; b2_gc = (const float*)d_in[19];
    } else {                  // grouped
        W1_cc = (const float*)d_in[8];
        W1_cg = (const float*)d_in[9];
        W1_gc = (const float*)d_in[10];
        W2_cc = (const float*)d_in[11];
        W2_gc = (const float*)d_in[13];
        b1_cc = (const float*)d_in[14];
        b1_cg = (const float*)d_in[15];
        b1_gc = (const float*)d_in[16];
        b2_cc = (const float*)d_in[17];
        b2_gc = (const float*)d_in[19];
    }

    int Nc = in_sizes[0] / FD;
    int Ng = in_sizes[1] / FD;
    int nEcc = in_sizes[2];
    int nEcg = in_sizes[4];
    int nEgc = in_sizes[6];

    __half* hs = nullptr;
    float* deg = nullptr;
    int* ints = nullptr;
    cudaGetSymbolAddress((void**)&hs, g_hscratch);
    cudaGetSymbolAddress((void**)&deg, g_deg);
    cudaGetSymbolAddress((void**)&ints, g_int);

    __half* Ycc = hs + HOFF_YCC;
    __half* Ycg = hs + HOFF_YCG;
    __half* Ygc = hs + HOFF_YGC;
    __half* h1c = hs + HOFF_H1C;
    __half* h1g = hs + HOFF_H1G;

    float* invs_cc = deg + DOFF_INVS_CC;
    float* invs_cg = deg + DOFF_INVS_CG;
    float* invs_gc = deg + DOFF_INVS_GC;
    float* invd_cc = deg + DOFF_INVD_CC;
    float* invd_gc = deg + DOFF_INVD_GC;
    float* invd_cg = deg + DOFF_INVD_CG;
    int* desc = (int*)(deg + DOFF_DESC);

    int* rp_cc = ints + IOFF_RP_CC;
    int* cur_cc = ints + IOFF_CUR_CC;
    int* rp_gc = ints + IOFF_RP_GC;
    int* cur_gc = ints + IOFF_CUR_GC;
    int* rp_cg = ints + IOFF_RP_CG;
    int* cur_cg = ints + IOFF_CUR_CG;
    int* col_cc = ints + IOFF_COL_CC;
    int* col_gc = ints + IOFF_COL_GC;
    int* col_cg = ints + IOFF_COL_CG;

    float* out = (float*)d_out;

    // ---- zero degrees + scan descriptors ----
    cudaMemsetAsync(deg, 0, DEG_TOTAL * sizeof(float), 0);

    // ---- degree histograms ----
    int nEtot = nEcc + nEcg + nEgc;
    deg_all<<<(nEtot + 255) / 256, 256>>>(src_cc, dst_cc, nEcc, invs_cc, invd_cc,
                                          src_cg, dst_cg, nEcg, invs_cg, invd_cg,
                                          src_gc, dst_gc, nEgc, invs_gc, invd_gc);

    // ---- single-kernel decoupled-lookback scan (+ fused rsqrt) ----
    int nb0 = (Nc + SCAN_TILE - 1) / SCAN_TILE;
    int nb1 = (Nc + SCAN_TILE - 1) / SCAN_TILE;
    int nb2 = (Ng + SCAN_TILE - 1) / SCAN_TILE;
    int nbT = nb0 + nb1 + nb2;
    int nrs = (INVS_TOTAL + SCAN_TILE - 1) / SCAN_TILE;
    scan_fused<<<nbT + nrs, 256>>>(invd_cc, Nc, rp_cc, cur_cc,
                                   invd_gc, Nc, rp_gc, cur_gc,
                                   invd_cg, Ng, rp_cg, cur_cg,
                                   nb0, nb1, nbT, desc,
                                   deg, INVS_TOTAL);
    fill_all<<<(nEtot + 255) / 256, 256>>>(src_cc, dst_cc, nEcc, cur_cc, col_cc,
                                           src_gc, dst_gc, nEgc, cur_gc, col_gc,
                                           src_cg, dst_cg, nEcg, cur_cg, col_cg);

    // ---- layer 1: all three GEMMs in one grid (fp32 in -> fp16 mma -> fp16 out) ----
    int gBlkC = (Nc + 127) / 128;
    int gBlkG = (Ng + 127) / 128;
    sgemm_h16_3<0><<<2 * gBlkC + gBlkG, 256>>>(
        x_chem, W1_cc, invs_cc, Ycc, Nc, gBlkC,
        x_chem, W1_cg, invs_cg, Ycg, Nc, gBlkC,
        x_gene, W1_gc, invs_gc, Ygc, Ng);

    // ---- layer 1: fused gathers ----
    gather_l1<<<(Nc + Ng + 7) / 8, 256>>>(rp_cc, col_cc, Ycc, invd_cc, b1_cc,
                                          rp_gc, col_gc, Ygc, invd_gc, b1_gc,
                                          h1c, Nc,
                                          rp_cg, col_cg, Ycg, invd_cg, b1_cg,
                                          h1g, Ng);

    // ---- layer 2: both GEMMs in one grid (fp16 in, fp16 out) ----
    sgemm_h16_3<1><<<gBlkC + gBlkG, 256>>>(
        h1c, W2_cc, invs_cc, Ycc, Nc, gBlkC,
        h1g, W2_gc, invs_gc, Ygc, Ng, gBlkG,
        (const void*)nullptr, (const float*)nullptr, (const float*)nullptr,
        (__half*)nullptr, 0);

    // ---- layer 2: gather -> fp32 output ----
    gather_l2<<<(Nc + 7) / 8, 256>>>(rp_cc, col_cc, Ycc, invd_cc, b2_cc,
                                     rp_gc, col_gc, Ygc, invd_gc, b2_gc,
                                     out, Nc);
}